// round 2
// baseline (speedup 1.0000x reference)
#include <cuda_runtime.h>
#include <cuda_bf16.h>
#include <math.h>

// Problem constants
#define BB   2
#define NN   2048
#define DIM  512
#define HH   8
#define DH   64
#define INNER 512          // H*DH
#define QKV3 1536          // 3*INNER
#define MROWS (BB*NN)      // 4096

typedef unsigned long long u64;

// Scratch (device globals; no allocation allowed)
__device__ float g_qkv[MROWS * QKV3];   // 24 MB  [b*N+i][3*INNER]
__device__ float g_att[MROWS * INNER];  //  8 MB  [b*N+i][h*64+d]

// ---------------- packed fp32x2 helpers (Blackwell FFMA2 path) ----------------
__device__ __forceinline__ void fma2(u64& d, u64 a, u64 b) {
    asm("fma.rn.f32x2 %0, %1, %2, %0;" : "+l"(d) : "l"(a), "l"(b));
}
__device__ __forceinline__ void mul2(u64& d, u64 a, u64 b) {
    asm("mul.rn.f32x2 %0, %1, %2;" : "=l"(d) : "l"(a), "l"(b));
}
__device__ __forceinline__ float2 u2f(u64 u) {
    float2 f;
    asm("mov.b64 {%0,%1}, %2;" : "=f"(f.x), "=f"(f.y) : "l"(u));
    return f;
}
__device__ __forceinline__ u64 f2u(float x, float y) {
    u64 u;
    asm("mov.b64 %0, {%1,%2};" : "=l"(u) : "f"(x), "f"(y));
    return u;
}

// ---------------------------------------------------------------------------
// fp32x2 GEMM: C[M,N] = A[M,K] @ B[K,N] (+bias). BM=BN=128, BK=16, 256 thr.
// Thread computes 8 rows x 4 column-pairs. A stored duplicated ((a,a) pairs)
// so the splat operand is a single LDS.64; B column-pairs swizzled 2*tx+32*g.
// ---------------------------------------------------------------------------
__global__ __launch_bounds__(256) void gemm128(const float* __restrict__ A,
                                               const float* __restrict__ B,
                                               const float* __restrict__ bias,
                                               float* __restrict__ C,
                                               int M, int N, int K)
{
    __shared__ float As[16][258];   // As[k][2m]=As[k][2m+1]=A[bm+m][k]
    __shared__ float Bs[16][132];   // Bs[k][n]

    const int bm = blockIdx.y * 128;
    const int bn = blockIdx.x * 128;
    const int tid = threadIdx.x;
    const int tx = tid & 15;
    const int ty = tid >> 4;

    u64 acc[8][4];
#pragma unroll
    for (int i = 0; i < 8; i++)
#pragma unroll
        for (int g = 0; g < 4; g++) acc[i][g] = 0ull;

    const int am  = tid >> 1;           // 0..127
    const int ak  = (tid & 1) * 8;      // 0 or 8
    const int bk  = tid >> 4;           // 0..15
    const int bc  = (tid & 15) * 8;     // 0..120

    for (int k0 = 0; k0 < K; k0 += 16) {
        // stage loads in registers
        float4 av0 = *reinterpret_cast<const float4*>(&A[(size_t)(bm + am) * K + k0 + ak]);
        float4 av1 = *reinterpret_cast<const float4*>(&A[(size_t)(bm + am) * K + k0 + ak + 4]);
        float4 bv0 = *reinterpret_cast<const float4*>(&B[(size_t)(k0 + bk) * N + bn + bc]);
        float4 bv1 = *reinterpret_cast<const float4*>(&B[(size_t)(k0 + bk) * N + bn + bc + 4]);
        __syncthreads();
        {
            float av[8] = {av0.x, av0.y, av0.z, av0.w, av1.x, av1.y, av1.z, av1.w};
#pragma unroll
            for (int q = 0; q < 8; q++) {
                As[ak + q][2 * am]     = av[q];
                As[ak + q][2 * am + 1] = av[q];
            }
            *reinterpret_cast<float4*>(&Bs[bk][bc])     = bv0;
            *reinterpret_cast<float4*>(&Bs[bk][bc + 4]) = bv1;
        }
        __syncthreads();

#pragma unroll
        for (int kk = 0; kk < 16; kk++) {
            u64 a[8], b[4];
#pragma unroll
            for (int i = 0; i < 8; i++)
                a[i] = *reinterpret_cast<const u64*>(&As[kk][2 * (ty * 8 + i)]);
#pragma unroll
            for (int g = 0; g < 4; g++)
                b[g] = *reinterpret_cast<const u64*>(&Bs[kk][2 * tx + 32 * g]);
#pragma unroll
            for (int i = 0; i < 8; i++)
#pragma unroll
                for (int g = 0; g < 4; g++) fma2(acc[i][g], a[i], b[g]);
        }
    }

#pragma unroll
    for (int i = 0; i < 8; i++) {
        const int row = bm + ty * 8 + i;
#pragma unroll
        for (int g = 0; g < 4; g++) {
            const int col = bn + 2 * tx + 32 * g;
            float2 v = u2f(acc[i][g]);
            if (bias) { v.x += bias[col]; v.y += bias[col + 1]; }
            *reinterpret_cast<float2*>(&C[(size_t)row * N + col]) = v;
        }
    }
}

// ---------------------------------------------------------------------------
// Flash-style masked attention with fp32x2 inner products.
// grid = (N/64, B*H); block 256. Each block: 64 q-rows of one (b,h).
// Thread tile: 4 q-rows x 4 key/d cols (2 pairs at cols 2*tx+32*g).
// ---------------------------------------------------------------------------
#define QD_LD 130
#define KT_LD 66
#define VS_LD 68
#define PD_LD 130
#define ATT_SMEM_FLOATS (64*QD_LD + 64*KT_LD + 64*VS_LD + 64*PD_LD)
#define ATT_SMEM_BYTES  (ATT_SMEM_FLOATS * 4)

__global__ __launch_bounds__(256) void attn_kernel(const float* __restrict__ qkv,
                                                   const int* __restrict__ mask_np,
                                                   const int* __restrict__ mask_bert,
                                                   float* __restrict__ out)
{
    extern __shared__ float sm[];
    float* Qd = sm;                       // [64][130] Q duplicated along d
    float* Kt = Qd + 64 * QD_LD;          // [64 d][66 keys]  (K transposed)
    float* Vs = Kt + 64 * KT_LD;          // [64 key][68 d]
    float* Pd = Vs + 64 * VS_LD;          // [64 row][130] P duplicated along key
    __shared__ int mnpk[64];
    __shared__ int mbk[64];

    const int b  = blockIdx.y >> 3;
    const int h  = blockIdx.y & 7;
    const int q0 = blockIdx.x * 64;
    const int tid = threadIdx.x;
    const int tx = tid & 15;
    const int ty = tid >> 4;
    const float scale = 0.125f;           // 1/sqrt(64)

    // load Q tile duplicated: Qd[r][2d] = Qd[r][2d+1] = Q[r][d]
#pragma unroll
    for (int it = 0; it < 4; it++) {
        int lin = it * 256 + tid;
        int r = lin >> 4;
        int d4 = (lin & 15) * 4;
        float4 q = *reinterpret_cast<const float4*>(
            &qkv[((size_t)(b * NN + q0 + r)) * QKV3 + h * 64 + d4]);
        float qv[4] = {q.x, q.y, q.z, q.w};
#pragma unroll
        for (int j = 0; j < 4; j++) {
            Qd[r * QD_LD + 2 * (d4 + j)]     = qv[j];
            Qd[r * QD_LD + 2 * (d4 + j) + 1] = qv[j];
        }
    }

    int mi[4];
#pragma unroll
    for (int i = 0; i < 4; i++) mi[i] = mask_np[b * NN + q0 + ty * 4 + i];

    u64 O2[4][2];
    float m_r[4], l_r[4];
#pragma unroll
    for (int i = 0; i < 4; i++) {
        m_r[i] = -1e30f; l_r[i] = 0.0f;
        O2[i][0] = 0ull; O2[i][1] = 0ull;
    }

    for (int t = 0; t < NN / 64; t++) {
        const int k0 = t * 64;
        __syncthreads();   // prev tile's PV done before overwriting K/V/P

        // load K (transposed, d-major) and V tiles
#pragma unroll
        for (int it = 0; it < 4; it++) {
            int lin = it * 256 + tid;
            int r = lin >> 4;
            int d4 = (lin & 15) * 4;
            size_t base = ((size_t)(b * NN + k0 + r)) * QKV3 + h * 64 + d4;
            float4 kv = *reinterpret_cast<const float4*>(&qkv[base + INNER]);
            Kt[(d4 + 0) * KT_LD + r] = kv.x;
            Kt[(d4 + 1) * KT_LD + r] = kv.y;
            Kt[(d4 + 2) * KT_LD + r] = kv.z;
            Kt[(d4 + 3) * KT_LD + r] = kv.w;
            float4 vv = *reinterpret_cast<const float4*>(&qkv[base + 2 * INNER]);
            *reinterpret_cast<float4*>(&Vs[r * VS_LD + d4]) = vv;
        }
        if (tid < 64) {
            mnpk[tid] = mask_np[b * NN + k0 + tid];
            mbk[tid]  = mask_bert[b * NN + k0 + tid];
        }
        __syncthreads();

        // scores
        u64 s2[4][2];
#pragma unroll
        for (int i = 0; i < 4; i++) { s2[i][0] = 0ull; s2[i][1] = 0ull; }

#pragma unroll 8
        for (int kk = 0; kk < 64; kk++) {
            u64 a[4], bb[2];
#pragma unroll
            for (int i = 0; i < 4; i++)
                a[i] = *reinterpret_cast<const u64*>(&Qd[(ty * 4 + i) * QD_LD + 2 * kk]);
#pragma unroll
            for (int g = 0; g < 2; g++)
                bb[g] = *reinterpret_cast<const u64*>(&Kt[kk * KT_LD + 2 * tx + 32 * g]);
#pragma unroll
            for (int i = 0; i < 4; i++)
#pragma unroll
                for (int g = 0; g < 2; g++) fma2(s2[i][g], a[i], bb[g]);
        }

        // unpack, mask + scale  (cols: 2*tx+32*g and +1)
        float s[4][4];
        bool colbad[4];
#pragma unroll
        for (int g = 0; g < 2; g++) {
            int c0 = 2 * tx + 32 * g;
            colbad[2 * g + 0] = (mnpk[c0] == 0)     | (mbk[c0] == 1);
            colbad[2 * g + 1] = (mnpk[c0 + 1] == 0) | (mbk[c0 + 1] == 1);
        }
#pragma unroll
        for (int i = 0; i < 4; i++) {
            const bool rowbad = (mi[i] == 0);
#pragma unroll
            for (int g = 0; g < 2; g++) {
                float2 f = u2f(s2[i][g]);
                s[i][2 * g + 0] = (rowbad | colbad[2 * g + 0]) ? -1000.0f : f.x * scale;
                s[i][2 * g + 1] = (rowbad | colbad[2 * g + 1]) ? -1000.0f : f.y * scale;
            }
        }

        // online softmax
        float p[4][4];
#pragma unroll
        for (int i = 0; i < 4; i++) {
            float mx = fmaxf(fmaxf(s[i][0], s[i][1]), fmaxf(s[i][2], s[i][3]));
#pragma unroll
            for (int off = 8; off >= 1; off >>= 1)
                mx = fmaxf(mx, __shfl_xor_sync(0xffffffffu, mx, off));
            float mnew = fmaxf(m_r[i], mx);
            float alpha = __expf(m_r[i] - mnew);
            float ls = 0.0f;
#pragma unroll
            for (int j = 0; j < 4; j++) {
                p[i][j] = __expf(s[i][j] - mnew);
                ls += p[i][j];
            }
#pragma unroll
            for (int off = 8; off >= 1; off >>= 1)
                ls += __shfl_xor_sync(0xffffffffu, ls, off);
            l_r[i] = l_r[i] * alpha + ls;
            m_r[i] = mnew;
            u64 alph2 = f2u(alpha, alpha);
            mul2(O2[i][0], O2[i][0], alph2);
            mul2(O2[i][1], O2[i][1], alph2);
        }

        // publish P duplicated along key dim
#pragma unroll
        for (int i = 0; i < 4; i++) {
#pragma unroll
            for (int g = 0; g < 2; g++) {
                int c0 = 2 * tx + 32 * g;
                *reinterpret_cast<u64*>(&Pd[(ty * 4 + i) * PD_LD + 2 * c0]) =
                    f2u(p[i][2 * g + 0], p[i][2 * g + 0]);
                *reinterpret_cast<u64*>(&Pd[(ty * 4 + i) * PD_LD + 2 * (c0 + 1)]) =
                    f2u(p[i][2 * g + 1], p[i][2 * g + 1]);
            }
        }
        __syncthreads();

        // O += P @ V
#pragma unroll 8
        for (int c = 0; c < 64; c++) {
            u64 pp[4], vv2[2];
#pragma unroll
            for (int i = 0; i < 4; i++)
                pp[i] = *reinterpret_cast<const u64*>(&Pd[(ty * 4 + i) * PD_LD + 2 * c]);
#pragma unroll
            for (int g = 0; g < 2; g++)
                vv2[g] = *reinterpret_cast<const u64*>(&Vs[c * VS_LD + 2 * tx + 32 * g]);
#pragma unroll
            for (int i = 0; i < 4; i++)
#pragma unroll
                for (int g = 0; g < 2; g++) fma2(O2[i][g], pp[i], vv2[g]);
        }
    }

    // normalize + write
#pragma unroll
    for (int i = 0; i < 4; i++) {
        const int row = q0 + ty * 4 + i;
        const float inv_l = 1.0f / l_r[i];
#pragma unroll
        for (int g = 0; g < 2; g++) {
            float2 o = u2f(O2[i][g]);
            float2 w; w.x = o.x * inv_l; w.y = o.y * inv_l;
            *reinterpret_cast<float2*>(
                &out[((size_t)(b * NN + row)) * INNER + h * 64 + 2 * tx + 32 * g]) = w;
        }
    }
}

// ---------------------------------------------------------------------------
extern "C" void kernel_launch(void* const* d_in, const int* in_sizes, int n_in,
                              void* d_out, int out_size)
{
    const float* x     = (const float*)d_in[0];
    const int*   mnp   = (const int*)d_in[1];
    const int*   mbert = (const int*)d_in[2];
    const float* Wqkv  = (const float*)d_in[3];
    const float* Wout  = (const float*)d_in[4];
    const float* bout  = (const float*)d_in[5];
    float* out = (float*)d_out;

    float *qkv_ptr, *att_ptr;
    cudaGetSymbolAddress((void**)&qkv_ptr, g_qkv);
    cudaGetSymbolAddress((void**)&att_ptr, g_att);

    cudaFuncSetAttribute(attn_kernel, cudaFuncAttributeMaxDynamicSharedMemorySize,
                         ATT_SMEM_BYTES);

    // 1) qkv = x @ W_qkv
    gemm128<<<dim3(QKV3 / 128, MROWS / 128), 256>>>(x, Wqkv, nullptr, qkv_ptr,
                                                    MROWS, QKV3, DIM);
    // 2) masked flash attention
    attn_kernel<<<dim3(NN / 64, BB * HH), 256, ATT_SMEM_BYTES>>>(qkv_ptr, mnp, mbert,
                                                                 att_ptr);
    // 3) out = att @ W_out + b_out
    gemm128<<<dim3(DIM / 128, MROWS / 128), 256>>>(att_ptr, Wout, bout, out,
                                                   MROWS, DIM, INNER);
}

// round 3
// speedup vs baseline: 2.1567x; 2.1567x over previous
#include <cuda_runtime.h>
#include <cuda_bf16.h>
#include <math.h>

#define BB    2
#define NN    2048
#define DIM   512
#define HH    8
#define DH    64
#define INNER 512
#define QKV3  1536
#define MROWS (BB*NN)      // 4096

typedef __nv_bfloat16 bf16;

// ---------------- device scratch (no allocation allowed) ----------------
__device__ bf16 g_x_h[MROWS * DIM],    g_x_l[MROWS * DIM];
__device__ bf16 g_wqkv_h[DIM * QKV3],  g_wqkv_l[DIM * QKV3];
__device__ bf16 g_wout_h[INNER * DIM], g_wout_l[INNER * DIM];
__device__ bf16 g_qkv_h[MROWS * QKV3], g_qkv_l[MROWS * QKV3];
__device__ bf16 g_att_h[MROWS * INNER], g_att_l[MROWS * INNER];

// ---------------- helpers ----------------
__device__ __forceinline__ unsigned pr(const bf16* p) {
    return *reinterpret_cast<const unsigned*>(p);
}
__device__ __forceinline__ void mma_bf16(float* c, const unsigned* a, unsigned b0, unsigned b1) {
    asm volatile(
        "mma.sync.aligned.m16n8k16.row.col.f32.bf16.bf16.f32 "
        "{%0,%1,%2,%3}, {%4,%5,%6,%7}, {%8,%9}, {%0,%1,%2,%3};"
        : "+f"(c[0]), "+f"(c[1]), "+f"(c[2]), "+f"(c[3])
        : "r"(a[0]), "r"(a[1]), "r"(a[2]), "r"(a[3]), "r"(b0), "r"(b1));
}
__device__ __forceinline__ unsigned pack2(bf16 a, bf16 b) {
    __nv_bfloat162 v; v.x = a; v.y = b;
    return *reinterpret_cast<unsigned*>(&v);
}
__device__ __forceinline__ void split1(float v, bf16& h, bf16& l) {
    h = __float2bfloat16(v);
    l = __float2bfloat16(v - __bfloat162float(h));
}

// ---------------- prep: fp32 -> bf16 hi/lo split ----------------
__global__ void split_kernel(const float* __restrict__ src, bf16* __restrict__ hi,
                             bf16* __restrict__ lo, int n)
{
    for (int i = blockIdx.x * blockDim.x + threadIdx.x; i < n; i += gridDim.x * blockDim.x) {
        float v = src[i];
        bf16 h, l; split1(v, h, l);
        hi[i] = h; lo[i] = l;
    }
}

// ---------------------------------------------------------------------------
// bf16x3 GEMM: C[M,N] = (Ah+Al)(Bh+Bl) ~= AhBh + AhBl + AlBh.
// Block 128x128, K-step 32, 256 threads (8 warps, warp tile 32x64).
// mode 0: C fp32 = acc + bias; mode 1: C split to (outh, outl) bf16.
// ---------------------------------------------------------------------------
#define ALD 40
#define BLD 36
__global__ __launch_bounds__(256) void gemm_mma(const bf16* __restrict__ Ah,
                                                const bf16* __restrict__ Al,
                                                const bf16* __restrict__ Bh,
                                                const bf16* __restrict__ Bl,
                                                const float* __restrict__ bias,
                                                float* __restrict__ outf,
                                                bf16* __restrict__ outh,
                                                bf16* __restrict__ outl,
                                                int M, int N, int K, int mode)
{
    __shared__ bf16 sAh[128][ALD], sAl[128][ALD];
    __shared__ bf16 sBh[128][BLD], sBl[128][BLD];

    const int bm = blockIdx.y * 128;
    const int bn = blockIdx.x * 128;
    const int tid = threadIdx.x;
    const int warp = tid >> 5;
    const int lane = tid & 31;
    const int g = lane >> 2;
    const int t = lane & 3;
    const int wm = warp & 3;           // 4 row groups of 32
    const int wn = warp >> 2;          // 2 col groups of 64
    const int rowbase = wm * 32;
    const int colbase = wn * 64;

    float acc[2][8][4];
#pragma unroll
    for (int mt = 0; mt < 2; mt++)
#pragma unroll
        for (int nt = 0; nt < 8; nt++)
#pragma unroll
            for (int i = 0; i < 4; i++) acc[mt][nt][i] = 0.0f;

    const int ar = tid >> 1;            // 0..127
    const int ac = (tid & 1) * 16;      // 0 or 16
    const int bk = tid >> 3;            // 0..31
    const int bn0 = (tid & 7) * 16;     // 0..112

    for (int k0 = 0; k0 < K; k0 += 32) {
        uint4 avh0 = *reinterpret_cast<const uint4*>(&Ah[(size_t)(bm + ar) * K + k0 + ac]);
        uint4 avh1 = *reinterpret_cast<const uint4*>(&Ah[(size_t)(bm + ar) * K + k0 + ac + 8]);
        uint4 avl0 = *reinterpret_cast<const uint4*>(&Al[(size_t)(bm + ar) * K + k0 + ac]);
        uint4 avl1 = *reinterpret_cast<const uint4*>(&Al[(size_t)(bm + ar) * K + k0 + ac + 8]);
        uint4 bvh0 = *reinterpret_cast<const uint4*>(&Bh[(size_t)(k0 + bk) * N + bn + bn0]);
        uint4 bvh1 = *reinterpret_cast<const uint4*>(&Bh[(size_t)(k0 + bk) * N + bn + bn0 + 8]);
        uint4 bvl0 = *reinterpret_cast<const uint4*>(&Bl[(size_t)(k0 + bk) * N + bn + bn0]);
        uint4 bvl1 = *reinterpret_cast<const uint4*>(&Bl[(size_t)(k0 + bk) * N + bn + bn0 + 8]);
        __syncthreads();   // previous iteration's MMAs done
        *reinterpret_cast<uint4*>(&sAh[ar][ac])     = avh0;
        *reinterpret_cast<uint4*>(&sAh[ar][ac + 8]) = avh1;
        *reinterpret_cast<uint4*>(&sAl[ar][ac])     = avl0;
        *reinterpret_cast<uint4*>(&sAl[ar][ac + 8]) = avl1;
        {
            const bf16* p0 = reinterpret_cast<const bf16*>(&bvh0);
            const bf16* p1 = reinterpret_cast<const bf16*>(&bvh1);
            const bf16* q0 = reinterpret_cast<const bf16*>(&bvl0);
            const bf16* q1 = reinterpret_cast<const bf16*>(&bvl1);
#pragma unroll
            for (int i = 0; i < 8; i++) {
                sBh[bn0 + i][bk]     = p0[i];
                sBh[bn0 + 8 + i][bk] = p1[i];
                sBl[bn0 + i][bk]     = q0[i];
                sBl[bn0 + 8 + i][bk] = q1[i];
            }
        }
        __syncthreads();

#pragma unroll
        for (int kc = 0; kc < 2; kc++) {
            unsigned a_h[2][4], a_l[2][4];
#pragma unroll
            for (int mt = 0; mt < 2; mt++) {
                const int rb = rowbase + mt * 16;
                const int cc = kc * 16 + 2 * t;
                a_h[mt][0] = pr(&sAh[rb + g][cc]);
                a_h[mt][1] = pr(&sAh[rb + g + 8][cc]);
                a_h[mt][2] = pr(&sAh[rb + g][cc + 8]);
                a_h[mt][3] = pr(&sAh[rb + g + 8][cc + 8]);
                a_l[mt][0] = pr(&sAl[rb + g][cc]);
                a_l[mt][1] = pr(&sAl[rb + g + 8][cc]);
                a_l[mt][2] = pr(&sAl[rb + g][cc + 8]);
                a_l[mt][3] = pr(&sAl[rb + g + 8][cc + 8]);
            }
#pragma unroll
            for (int nt = 0; nt < 8; nt++) {
                const int nr = colbase + nt * 8 + g;
                const int cc = kc * 16 + 2 * t;
                unsigned bh0 = pr(&sBh[nr][cc]);
                unsigned bh1 = pr(&sBh[nr][cc + 8]);
                unsigned bl0 = pr(&sBl[nr][cc]);
                unsigned bl1 = pr(&sBl[nr][cc + 8]);
#pragma unroll
                for (int mt = 0; mt < 2; mt++) {
                    mma_bf16(acc[mt][nt], a_h[mt], bh0, bh1);
                    mma_bf16(acc[mt][nt], a_h[mt], bl0, bl1);
                    mma_bf16(acc[mt][nt], a_l[mt], bh0, bh1);
                }
            }
        }
    }

    // epilogue
#pragma unroll
    for (int mt = 0; mt < 2; mt++) {
        const int r0 = bm + rowbase + mt * 16 + g;
        const int r1 = r0 + 8;
#pragma unroll
        for (int nt = 0; nt < 8; nt++) {
            const int c0 = bn + colbase + nt * 8 + 2 * t;
            float v0 = acc[mt][nt][0], v1 = acc[mt][nt][1];
            float v2 = acc[mt][nt][2], v3 = acc[mt][nt][3];
            if (mode == 0) {
                float b0 = bias[c0], b1 = bias[c0 + 1];
                *reinterpret_cast<float2*>(&outf[(size_t)r0 * N + c0]) = make_float2(v0 + b0, v1 + b1);
                *reinterpret_cast<float2*>(&outf[(size_t)r1 * N + c0]) = make_float2(v2 + b0, v3 + b1);
            } else {
                bf16 h0, l0, h1, l1, h2, l2, h3, l3;
                split1(v0, h0, l0); split1(v1, h1, l1);
                split1(v2, h2, l2); split1(v3, h3, l3);
                *reinterpret_cast<unsigned*>(&outh[(size_t)r0 * N + c0]) = pack2(h0, h1);
                *reinterpret_cast<unsigned*>(&outl[(size_t)r0 * N + c0]) = pack2(l0, l1);
                *reinterpret_cast<unsigned*>(&outh[(size_t)r1 * N + c0]) = pack2(h2, h3);
                *reinterpret_cast<unsigned*>(&outl[(size_t)r1 * N + c0]) = pack2(l2, l3);
            }
        }
    }
}

// ---------------------------------------------------------------------------
// Attention: 128 q-rows per block, 64-key tiles, bf16x3 MMA QK & PV.
// Fixed-shift softmax (no online max): p = exp(masked ? -1000 : s*scale, + 1000
// if the q-row is dead) -> exact reference semantics incl. fully-masked rows.
// Block 256 thr = 8 warps; warp owns 16 q-rows. O accumulates in registers.
// ---------------------------------------------------------------------------
#define SLD 72      // padded row length (bf16 elems) for all attn smem tiles
#define OFF_QH  0
#define OFF_QL  (OFF_QH + 128*SLD)
#define OFF_KH  (OFF_QL + 128*SLD)
#define OFF_KL  (OFF_KH + 64*SLD)
#define OFF_VTH (OFF_KL + 64*SLD)
#define OFF_VTL (OFF_VTH + 64*SLD)
#define OFF_PH  (OFF_VTL + 64*SLD)
#define OFF_PL  (OFF_PH + 128*SLD)
#define ATT_BF16S (OFF_PL + 128*SLD)
#define ATT_SMEM_BYTES (ATT_BF16S*2 + 64*4)

__global__ __launch_bounds__(256) void attn_mma(const bf16* __restrict__ qh,
                                                const bf16* __restrict__ ql,
                                                const int* __restrict__ mask_np,
                                                const int* __restrict__ mask_bert,
                                                bf16* __restrict__ outh,
                                                bf16* __restrict__ outl)
{
    extern __shared__ char smraw[];
    bf16* sm = reinterpret_cast<bf16*>(smraw);
    bf16* QH = sm + OFF_QH;  bf16* QL = sm + OFF_QL;
    bf16* KH = sm + OFF_KH;  bf16* KL = sm + OFF_KL;
    bf16* VTH = sm + OFF_VTH; bf16* VTL = sm + OFF_VTL;
    bf16* PH = sm + OFF_PH;  bf16* PL = sm + OFF_PL;
    int* colpen = reinterpret_cast<int*>(smraw + ATT_BF16S * 2);

    const int b  = blockIdx.y >> 3;
    const int h  = blockIdx.y & 7;
    const int q0 = blockIdx.x * 128;
    const int tid = threadIdx.x;
    const int warp = tid >> 5;
    const int lane = tid & 31;
    const int g = lane >> 2;
    const int t = lane & 3;
    const int rb = warp * 16;            // warp's q-row base within block
    const float scale = 0.125f;

    // ---- load Q (hi/lo) into smem ----
    {
        const int r  = tid >> 1;
        const int d0 = (tid & 1) * 32;
        const size_t base = (size_t)(b * NN + q0 + r) * QKV3 + h * 64 + d0;
#pragma unroll
        for (int j = 0; j < 4; j++) {
            *reinterpret_cast<uint4*>(&QH[r * SLD + d0 + 8 * j]) =
                *reinterpret_cast<const uint4*>(&qh[base + 8 * j]);
            *reinterpret_cast<uint4*>(&QL[r * SLD + d0 + 8 * j]) =
                *reinterpret_cast<const uint4*>(&ql[base + 8 * j]);
        }
    }

    // row masks for this lane's two rows
    const int rowbad0 = (mask_np[b * NN + q0 + rb + g] == 0);
    const int rowbad8 = (mask_np[b * NN + q0 + rb + g + 8] == 0);
    const float shift0 = rowbad0 ? 1000.0f : 0.0f;
    const float shift8 = rowbad8 ? 1000.0f : 0.0f;

    float O[8][4];
#pragma unroll
    for (int nt = 0; nt < 8; nt++)
#pragma unroll
        for (int i = 0; i < 4; i++) O[nt][i] = 0.0f;
    float lsum0 = 0.0f, lsum8 = 0.0f;

    const int kkey = tid >> 2;           // 0..63
    const int kd0  = (tid & 3) * 16;     // 0,16,32,48

    unsigned aqh[4][4], aql[4][4];       // Q fragments, loaded once (after first sync)
    bool qfrag_loaded = false;

    for (int kt = 0; kt < NN / 64; kt++) {
        const int kt0 = kt * 64;
        // global loads into registers
        const size_t kbase = (size_t)(b * NN + kt0 + kkey) * QKV3 + INNER + h * 64 + kd0;
        const size_t vbase = kbase + INNER;
        uint4 kvh0 = *reinterpret_cast<const uint4*>(&qh[kbase]);
        uint4 kvh1 = *reinterpret_cast<const uint4*>(&qh[kbase + 8]);
        uint4 kvl0 = *reinterpret_cast<const uint4*>(&ql[kbase]);
        uint4 kvl1 = *reinterpret_cast<const uint4*>(&ql[kbase + 8]);
        uint4 vvh0 = *reinterpret_cast<const uint4*>(&qh[vbase]);
        uint4 vvh1 = *reinterpret_cast<const uint4*>(&qh[vbase + 8]);
        uint4 vvl0 = *reinterpret_cast<const uint4*>(&ql[vbase]);
        uint4 vvl1 = *reinterpret_cast<const uint4*>(&ql[vbase + 8]);
        int cp = 0;
        if (tid < 64)
            cp = (mask_np[b * NN + kt0 + tid] == 0) | (mask_bert[b * NN + kt0 + tid] == 1);

        __syncthreads();   // previous tile's PV complete
        *reinterpret_cast<uint4*>(&KH[kkey * SLD + kd0])     = kvh0;
        *reinterpret_cast<uint4*>(&KH[kkey * SLD + kd0 + 8]) = kvh1;
        *reinterpret_cast<uint4*>(&KL[kkey * SLD + kd0])     = kvl0;
        *reinterpret_cast<uint4*>(&KL[kkey * SLD + kd0 + 8]) = kvl1;
        {
            const bf16* ph0 = reinterpret_cast<const bf16*>(&vvh0);
            const bf16* ph1 = reinterpret_cast<const bf16*>(&vvh1);
            const bf16* pl0 = reinterpret_cast<const bf16*>(&vvl0);
            const bf16* pl1 = reinterpret_cast<const bf16*>(&vvl1);
#pragma unroll
            for (int i = 0; i < 8; i++) {
                VTH[(kd0 + i) * SLD + kkey]     = ph0[i];
                VTH[(kd0 + 8 + i) * SLD + kkey] = ph1[i];
                VTL[(kd0 + i) * SLD + kkey]     = pl0[i];
                VTL[(kd0 + 8 + i) * SLD + kkey] = pl1[i];
            }
        }
        if (tid < 64) colpen[tid] = cp;
        __syncthreads();

        if (!qfrag_loaded) {
            qfrag_loaded = true;
#pragma unroll
            for (int kc = 0; kc < 4; kc++) {
                const int cc = kc * 16 + 2 * t;
                aqh[kc][0] = pr(&QH[(rb + g) * SLD + cc]);
                aqh[kc][1] = pr(&QH[(rb + g + 8) * SLD + cc]);
                aqh[kc][2] = pr(&QH[(rb + g) * SLD + cc + 8]);
                aqh[kc][3] = pr(&QH[(rb + g + 8) * SLD + cc + 8]);
                aql[kc][0] = pr(&QL[(rb + g) * SLD + cc]);
                aql[kc][1] = pr(&QL[(rb + g + 8) * SLD + cc]);
                aql[kc][2] = pr(&QL[(rb + g) * SLD + cc + 8]);
                aql[kc][3] = pr(&QL[(rb + g + 8) * SLD + cc + 8]);
            }
        }

        // ---- QK + softmax + P store ----
#pragma unroll
        for (int nt = 0; nt < 8; nt++) {
            float sc[4] = {0.0f, 0.0f, 0.0f, 0.0f};
#pragma unroll
            for (int kc = 0; kc < 4; kc++) {
                const int nr = nt * 8 + g;
                const int cc = kc * 16 + 2 * t;
                unsigned bh0 = pr(&KH[nr * SLD + cc]);
                unsigned bh1 = pr(&KH[nr * SLD + cc + 8]);
                unsigned bl0 = pr(&KL[nr * SLD + cc]);
                unsigned bl1 = pr(&KL[nr * SLD + cc + 8]);
                mma_bf16(sc, aqh[kc], bh0, bh1);
                mma_bf16(sc, aqh[kc], bl0, bl1);
                mma_bf16(sc, aql[kc], bh0, bh1);
            }
            const int cb0 = colpen[nt * 8 + 2 * t];
            const int cb1 = colpen[nt * 8 + 2 * t + 1];
            float x0 = (cb0 | rowbad0) ? -1000.0f : sc[0] * scale;
            float x1 = (cb1 | rowbad0) ? -1000.0f : sc[1] * scale;
            float x2 = (cb0 | rowbad8) ? -1000.0f : sc[2] * scale;
            float x3 = (cb1 | rowbad8) ? -1000.0f : sc[3] * scale;
            float p0 = __expf(x0 + shift0);
            float p1 = __expf(x1 + shift0);
            float p2 = __expf(x2 + shift8);
            float p3 = __expf(x3 + shift8);
            lsum0 += p0 + p1;
            lsum8 += p2 + p3;
            bf16 h0, l0, h1, l1, h2, l2, h3, l3;
            split1(p0, h0, l0); split1(p1, h1, l1);
            split1(p2, h2, l2); split1(p3, h3, l3);
            const int col = nt * 8 + 2 * t;
            *reinterpret_cast<unsigned*>(&PH[(rb + g) * SLD + col])     = pack2(h0, h1);
            *reinterpret_cast<unsigned*>(&PL[(rb + g) * SLD + col])     = pack2(l0, l1);
            *reinterpret_cast<unsigned*>(&PH[(rb + g + 8) * SLD + col]) = pack2(h2, h3);
            *reinterpret_cast<unsigned*>(&PL[(rb + g + 8) * SLD + col]) = pack2(l2, l3);
        }
        __syncwarp();      // P tile is warp-local (warp reads only its own rows)

        // ---- PV ----
#pragma unroll
        for (int kc = 0; kc < 4; kc++) {
            const int cc = kc * 16 + 2 * t;
            unsigned ph[4], pl[4];
            ph[0] = pr(&PH[(rb + g) * SLD + cc]);
            ph[1] = pr(&PH[(rb + g + 8) * SLD + cc]);
            ph[2] = pr(&PH[(rb + g) * SLD + cc + 8]);
            ph[3] = pr(&PH[(rb + g + 8) * SLD + cc + 8]);
            pl[0] = pr(&PL[(rb + g) * SLD + cc]);
            pl[1] = pr(&PL[(rb + g + 8) * SLD + cc]);
            pl[2] = pr(&PL[(rb + g) * SLD + cc + 8]);
            pl[3] = pr(&PL[(rb + g + 8) * SLD + cc + 8]);
#pragma unroll
            for (int nt = 0; nt < 8; nt++) {
                const int nr = nt * 8 + g;
                unsigned bh0 = pr(&VTH[nr * SLD + cc]);
                unsigned bh1 = pr(&VTH[nr * SLD + cc + 8]);
                unsigned bl0 = pr(&VTL[nr * SLD + cc]);
                unsigned bl1 = pr(&VTL[nr * SLD + cc + 8]);
                mma_bf16(O[nt], ph, bh0, bh1);
                mma_bf16(O[nt], ph, bl0, bl1);
                mma_bf16(O[nt], pl, bh0, bh1);
            }
        }
    }

    // ---- epilogue: reduce l across the quad, normalize, split-store ----
    lsum0 += __shfl_xor_sync(0xffffffffu, lsum0, 1);
    lsum0 += __shfl_xor_sync(0xffffffffu, lsum0, 2);
    lsum8 += __shfl_xor_sync(0xffffffffu, lsum8, 1);
    lsum8 += __shfl_xor_sync(0xffffffffu, lsum8, 2);
    const float inv0 = 1.0f / lsum0;
    const float inv8 = 1.0f / lsum8;

    const size_t row0 = (size_t)(b * NN + q0 + rb + g);
    const size_t row8 = row0 + 8;
#pragma unroll
    for (int nt = 0; nt < 8; nt++) {
        const int d = h * 64 + nt * 8 + 2 * t;
        float v0 = O[nt][0] * inv0, v1 = O[nt][1] * inv0;
        float v2 = O[nt][2] * inv8, v3 = O[nt][3] * inv8;
        bf16 h0, l0, h1, l1, h2, l2, h3, l3;
        split1(v0, h0, l0); split1(v1, h1, l1);
        split1(v2, h2, l2); split1(v3, h3, l3);
        *reinterpret_cast<unsigned*>(&outh[row0 * INNER + d]) = pack2(h0, h1);
        *reinterpret_cast<unsigned*>(&outl[row0 * INNER + d]) = pack2(l0, l1);
        *reinterpret_cast<unsigned*>(&outh[row8 * INNER + d]) = pack2(h2, h3);
        *reinterpret_cast<unsigned*>(&outl[row8 * INNER + d]) = pack2(l2, l3);
    }
}

// ---------------------------------------------------------------------------
extern "C" void kernel_launch(void* const* d_in, const int* in_sizes, int n_in,
                              void* d_out, int out_size)
{
    const float* x     = (const float*)d_in[0];
    const int*   mnp   = (const int*)d_in[1];
    const int*   mbert = (const int*)d_in[2];
    const float* Wqkv  = (const float*)d_in[3];
    const float* Wout  = (const float*)d_in[4];
    const float* bout  = (const float*)d_in[5];
    float* out = (float*)d_out;

    bf16 *xh, *xl, *wqh, *wql, *woh, *wol, *qkvh, *qkvl, *ath, *atl;
    cudaGetSymbolAddress((void**)&xh,   g_x_h);
    cudaGetSymbolAddress((void**)&xl,   g_x_l);
    cudaGetSymbolAddress((void**)&wqh,  g_wqkv_h);
    cudaGetSymbolAddress((void**)&wql,  g_wqkv_l);
    cudaGetSymbolAddress((void**)&woh,  g_wout_h);
    cudaGetSymbolAddress((void**)&wol,  g_wout_l);
    cudaGetSymbolAddress((void**)&qkvh, g_qkv_h);
    cudaGetSymbolAddress((void**)&qkvl, g_qkv_l);
    cudaGetSymbolAddress((void**)&ath,  g_att_h);
    cudaGetSymbolAddress((void**)&atl,  g_att_l);

    cudaFuncSetAttribute(attn_mma, cudaFuncAttributeMaxDynamicSharedMemorySize,
                         ATT_SMEM_BYTES);

    // prep: split inputs into bf16 hi/lo
    split_kernel<<<512, 256>>>(x,    xh,  xl,  MROWS * DIM);
    split_kernel<<<512, 256>>>(Wqkv, wqh, wql, DIM * QKV3);
    split_kernel<<<256, 256>>>(Wout, woh, wol, INNER * DIM);

    // 1) qkv = x @ W_qkv  -> bf16 hi/lo
    gemm_mma<<<dim3(QKV3 / 128, MROWS / 128), 256>>>(
        xh, xl, wqh, wql, nullptr, nullptr, qkvh, qkvl, MROWS, QKV3, DIM, 1);

    // 2) masked attention -> bf16 hi/lo
    attn_mma<<<dim3(NN / 128, BB * HH), 256, ATT_SMEM_BYTES>>>(
        qkvh, qkvl, mnp, mbert, ath, atl);

    // 3) out = att @ W_out + b_out  -> fp32
    gemm_mma<<<dim3(DIM / 128, MROWS / 128), 256>>>(
        ath, atl, woh, wol, bout, out, nullptr, nullptr, MROWS, DIM, INNER, 0);
}

// round 4
// speedup vs baseline: 3.0811x; 1.4286x over previous
#include <cuda_runtime.h>
#include <cuda_bf16.h>
#include <math.h>

#define BB    2
#define NN    2048
#define DIM   512
#define HH    8
#define DH    64
#define INNER 512
#define QKV3  1536
#define MROWS (BB*NN)      // 4096

typedef __nv_bfloat16 bf16;

// ---------------- device scratch (no allocation allowed) ----------------
__device__ bf16 g_x_h[MROWS * DIM],    g_x_l[MROWS * DIM];
__device__ bf16 g_wqkv_h[DIM * QKV3],  g_wqkv_l[DIM * QKV3];
__device__ bf16 g_wout_h[INNER * DIM], g_wout_l[INNER * DIM];
__device__ bf16 g_qkv_h[MROWS * QKV3], g_qkv_l[MROWS * QKV3];
__device__ bf16 g_att_h[MROWS * INNER], g_att_l[MROWS * INNER];

// ---------------- helpers ----------------
__device__ __forceinline__ unsigned s2u(const void* p) {
    return (unsigned)__cvta_generic_to_shared(p);
}
__device__ __forceinline__ void ldsm4(unsigned* r, const void* p) {
    asm volatile("ldmatrix.sync.aligned.m8n8.x4.shared.b16 {%0,%1,%2,%3}, [%4];"
        : "=r"(r[0]), "=r"(r[1]), "=r"(r[2]), "=r"(r[3]) : "r"(s2u(p)));
}
__device__ __forceinline__ void ldsm4t(unsigned* r, const void* p) {
    asm volatile("ldmatrix.sync.aligned.m8n8.x4.trans.shared.b16 {%0,%1,%2,%3}, [%4];"
        : "=r"(r[0]), "=r"(r[1]), "=r"(r[2]), "=r"(r[3]) : "r"(s2u(p)));
}
__device__ __forceinline__ void cp16(void* s, const void* g) {
    asm volatile("cp.async.cg.shared.global [%0], [%1], 16;" :: "r"(s2u(s)), "l"(g));
}
__device__ __forceinline__ void cp_commit() { asm volatile("cp.async.commit_group;"); }
template<int N> __device__ __forceinline__ void cp_wait() {
    asm volatile("cp.async.wait_group %0;" :: "n"(N));
}
__device__ __forceinline__ void mma_bf16(float* c, const unsigned* a, unsigned b0, unsigned b1) {
    asm volatile(
        "mma.sync.aligned.m16n8k16.row.col.f32.bf16.bf16.f32 "
        "{%0,%1,%2,%3}, {%4,%5,%6,%7}, {%8,%9}, {%0,%1,%2,%3};"
        : "+f"(c[0]), "+f"(c[1]), "+f"(c[2]), "+f"(c[3])
        : "r"(a[0]), "r"(a[1]), "r"(a[2]), "r"(a[3]), "r"(b0), "r"(b1));
}
__device__ __forceinline__ unsigned pack2(bf16 a, bf16 b) {
    __nv_bfloat162 v; v.x = a; v.y = b;
    return *reinterpret_cast<unsigned*>(&v);
}
__device__ __forceinline__ void split1(float v, bf16& h, bf16& l) {
    h = __float2bfloat16(v);
    l = __float2bfloat16(v - __bfloat162float(h));
}

// ---------------- prep: fp32 -> bf16 hi/lo split ----------------
__global__ void split_kernel(const float* __restrict__ src, bf16* __restrict__ hi,
                             bf16* __restrict__ lo, int n)
{
    for (int i = blockIdx.x * blockDim.x + threadIdx.x; i < n; i += gridDim.x * blockDim.x) {
        float v = src[i];
        bf16 h, l; split1(v, h, l);
        hi[i] = h; lo[i] = l;
    }
}

// ---------------------------------------------------------------------------
// bf16x3 GEMM, 128x128 block, BK=32, 256 thr (8 warps; warp tile 32x64).
// cp.async double-buffered; fragments via ldmatrix (A non-trans, B trans).
// ---------------------------------------------------------------------------
#define GALD 40
#define GBLD 136
#define G_SA(buf,hl) (sm + ((buf)*2 + (hl)) * (128*GALD))
#define G_SB(buf,hl) (sm + 4*128*GALD + ((buf)*2 + (hl)) * (32*GBLD))
#define GEMM_SMEM_BYTES ((4*128*GALD + 4*32*GBLD) * 2)

__global__ __launch_bounds__(256, 1) void gemm_mma(const bf16* __restrict__ Ah,
                                                   const bf16* __restrict__ Al,
                                                   const bf16* __restrict__ Bh,
                                                   const bf16* __restrict__ Bl,
                                                   const float* __restrict__ bias,
                                                   float* __restrict__ outf,
                                                   bf16* __restrict__ outh,
                                                   bf16* __restrict__ outl,
                                                   int M, int N, int K, int mode)
{
    extern __shared__ bf16 sm[];

    const int bm = blockIdx.y * 128;
    const int bn = blockIdx.x * 128;
    const int tid = threadIdx.x;
    const int warp = tid >> 5;
    const int lane = tid & 31;
    const int g = lane >> 2;
    const int t = lane & 3;
    const int rowbase = (warp & 3) * 32;
    const int colbase = (warp >> 2) * 64;

    float acc[2][8][4];
#pragma unroll
    for (int mt = 0; mt < 2; mt++)
#pragma unroll
        for (int nt = 0; nt < 8; nt++)
#pragma unroll
            for (int i = 0; i < 4; i++) acc[mt][nt][i] = 0.0f;

    // ldmatrix lane addressing
    const int tile = lane >> 3;
    const int trow = lane & 7;

    auto prefetch = [&](int buf, int k0) {
#pragma unroll
        for (int j = 0; j < 2; j++) {
            int c = tid * 2 + j;                 // 0..511
            int row = c >> 2, kch = (c & 3) * 8;
            size_t go = (size_t)(bm + row) * K + k0 + kch;
            cp16(&G_SA(buf, 0)[row * GALD + kch], &Ah[go]);
            cp16(&G_SA(buf, 1)[row * GALD + kch], &Al[go]);
        }
#pragma unroll
        for (int j = 0; j < 2; j++) {
            int c = tid * 2 + j;
            int kr = c >> 4, nch = (c & 15) * 8;
            size_t go = (size_t)(k0 + kr) * N + bn + nch;
            cp16(&G_SB(buf, 0)[kr * GBLD + nch], &Bh[go]);
            cp16(&G_SB(buf, 1)[kr * GBLD + nch], &Bl[go]);
        }
    };

    prefetch(0, 0);
    cp_commit();

    const int NIT = K / 32;
    int buf = 0;
    for (int it = 0; it < NIT; it++) {
        if (it + 1 < NIT) { prefetch(buf ^ 1, (it + 1) * 32); cp_commit(); cp_wait<1>(); }
        else cp_wait<0>();
        __syncthreads();

        const bf16* As_h = G_SA(buf, 0);
        const bf16* As_l = G_SA(buf, 1);
        const bf16* Bs_h = G_SB(buf, 0);
        const bf16* Bs_l = G_SB(buf, 1);

#pragma unroll
        for (int kc = 0; kc < 2; kc++) {
            unsigned ah[2][4], al[2][4];
            const int amrow = (tile & 1) * 8 + trow;
            const int akoff = kc * 16 + (tile >> 1) * 8;
#pragma unroll
            for (int mt = 0; mt < 2; mt++) {
                ldsm4(ah[mt], &As_h[(rowbase + mt * 16 + amrow) * GALD + akoff]);
                ldsm4(al[mt], &As_l[(rowbase + mt * 16 + amrow) * GALD + akoff]);
            }
            const int bkrow = kc * 16 + (tile & 1) * 8 + trow;
#pragma unroll
            for (int ntp = 0; ntp < 4; ntp++) {
                const int bncol = colbase + ntp * 16 + (tile >> 1) * 8;
                unsigned bh[4], bl[4];
                ldsm4t(bh, &Bs_h[bkrow * GBLD + bncol]);
                ldsm4t(bl, &Bs_l[bkrow * GBLD + bncol]);
#pragma unroll
                for (int q = 0; q < 2; q++) {
                    const int nt = ntp * 2 + q;
                    unsigned b0 = bh[q * 2], b1 = bh[q * 2 + 1];
                    unsigned c0 = bl[q * 2], c1 = bl[q * 2 + 1];
#pragma unroll
                    for (int mt = 0; mt < 2; mt++) {
                        mma_bf16(acc[mt][nt], ah[mt], b0, b1);
                        mma_bf16(acc[mt][nt], ah[mt], c0, c1);
                        mma_bf16(acc[mt][nt], al[mt], b0, b1);
                    }
                }
            }
        }
        __syncthreads();
        buf ^= 1;
    }

    // epilogue
#pragma unroll
    for (int mt = 0; mt < 2; mt++) {
        const int r0 = bm + rowbase + mt * 16 + g;
        const int r1 = r0 + 8;
#pragma unroll
        for (int nt = 0; nt < 8; nt++) {
            const int c0 = bn + colbase + nt * 8 + 2 * t;
            float v0 = acc[mt][nt][0], v1 = acc[mt][nt][1];
            float v2 = acc[mt][nt][2], v3 = acc[mt][nt][3];
            if (mode == 0) {
                float b0 = bias[c0], b1 = bias[c0 + 1];
                *reinterpret_cast<float2*>(&outf[(size_t)r0 * N + c0]) = make_float2(v0 + b0, v1 + b1);
                *reinterpret_cast<float2*>(&outf[(size_t)r1 * N + c0]) = make_float2(v2 + b0, v3 + b1);
            } else {
                bf16 h0, l0, h1, l1, h2, l2, h3, l3;
                split1(v0, h0, l0); split1(v1, h1, l1);
                split1(v2, h2, l2); split1(v3, h3, l3);
                *reinterpret_cast<unsigned*>(&outh[(size_t)r0 * N + c0]) = pack2(h0, h1);
                *reinterpret_cast<unsigned*>(&outl[(size_t)r0 * N + c0]) = pack2(l0, l1);
                *reinterpret_cast<unsigned*>(&outh[(size_t)r1 * N + c0]) = pack2(h2, h3);
                *reinterpret_cast<unsigned*>(&outl[(size_t)r1 * N + c0]) = pack2(l2, l3);
            }
        }
    }
}

// ---------------------------------------------------------------------------
// Attention: 128 q-rows/block, 64-key tiles, cp.async double-buffered K/V,
// ldmatrix fragments, P converted register-to-register (no smem round trip).
// ---------------------------------------------------------------------------
#define ASLD 72
#define A_Q(hl)     (sm + (hl) * (128 * ASLD))
#define A_KV(buf,m) (sm + 2 * 128 * ASLD + ((buf) * 4 + (m)) * (64 * ASLD))
#define ATT_BF16_TOT (2 * 128 * ASLD + 8 * 64 * ASLD)
#define ATT_SMEM_BYTES (ATT_BF16_TOT * 2 + 2 * 2 * 64 * 4)

__global__ __launch_bounds__(256, 1) void attn_mma(const bf16* __restrict__ qh,
                                                   const bf16* __restrict__ ql,
                                                   const int* __restrict__ mask_np,
                                                   const int* __restrict__ mask_bert,
                                                   bf16* __restrict__ outh,
                                                   bf16* __restrict__ outl)
{
    extern __shared__ char smraw[];
    bf16* sm = reinterpret_cast<bf16*>(smraw);
    int* mint = reinterpret_cast<int*>(smraw + ATT_BF16_TOT * 2);
    // masks: [buf][np/bt][64]
    auto m_np = [&](int buf) { return mint + buf * 128; };
    auto m_bt = [&](int buf) { return mint + buf * 128 + 64; };

    const int b  = blockIdx.y >> 3;
    const int h  = blockIdx.y & 7;
    const int q0 = blockIdx.x * 128;
    const int tid = threadIdx.x;
    const int warp = tid >> 5;
    const int lane = tid & 31;
    const int g = lane >> 2;
    const int t = lane & 3;
    const int rb = warp * 16;
    const float scale = 0.125f;
    const int tile = lane >> 3;
    const int trow = lane & 7;

    // Q prefetch (group 0)
#pragma unroll
    for (int j = 0; j < 4; j++) {
        int c = tid * 4 + j;                  // 0..1023
        int row = c >> 3, dch = (c & 7) * 8;
        size_t base = (size_t)(b * NN + q0 + row) * QKV3 + h * 64 + dch;
        cp16(&A_Q(0)[row * ASLD + dch], &qh[base]);
        cp16(&A_Q(1)[row * ASLD + dch], &ql[base]);
    }
    cp_commit();

    auto pref = [&](int buf, int kt0) {
#pragma unroll
        for (int j = 0; j < 2; j++) {
            int c = tid * 2 + j;              // 0..511
            int row = c >> 3, dch = (c & 7) * 8;
            size_t kb = (size_t)(b * NN + kt0 + row) * QKV3 + INNER + h * 64 + dch;
            size_t vb = kb + INNER;
            cp16(&A_KV(buf, 0)[row * ASLD + dch], &qh[kb]);
            cp16(&A_KV(buf, 1)[row * ASLD + dch], &ql[kb]);
            cp16(&A_KV(buf, 2)[row * ASLD + dch], &qh[vb]);
            cp16(&A_KV(buf, 3)[row * ASLD + dch], &ql[vb]);
        }
        if (tid < 16) {
            cp16(&m_np(buf)[tid * 4], &mask_np[b * NN + kt0 + tid * 4]);
            cp16(&m_bt(buf)[tid * 4], &mask_bert[b * NN + kt0 + tid * 4]);
        }
    };
    pref(0, 0);
    cp_commit();

    const int rowbad0 = (mask_np[b * NN + q0 + rb + g] == 0);
    const int rowbad8 = (mask_np[b * NN + q0 + rb + g + 8] == 0);
    const float shift0 = rowbad0 ? 1000.0f : 0.0f;
    const float shift8 = rowbad8 ? 1000.0f : 0.0f;

    float O[8][4];
#pragma unroll
    for (int nt = 0; nt < 8; nt++)
#pragma unroll
        for (int i = 0; i < 4; i++) O[nt][i] = 0.0f;
    float lsum0 = 0.0f, lsum8 = 0.0f;

    unsigned aqh[4][4], aql[4][4];

    int buf = 0;
    for (int kt = 0; kt < NN / 64; kt++) {
        if (kt + 1 < NN / 64) { pref(buf ^ 1, (kt + 1) * 64); cp_commit(); cp_wait<1>(); }
        else cp_wait<0>();
        __syncthreads();

        if (kt == 0) {
            const int qr = rb + (tile & 1) * 8 + trow;
#pragma unroll
            for (int kc = 0; kc < 4; kc++) {
                ldsm4(aqh[kc], &A_Q(0)[qr * ASLD + kc * 16 + (tile >> 1) * 8]);
                ldsm4(aql[kc], &A_Q(1)[qr * ASLD + kc * 16 + (tile >> 1) * 8]);
            }
        }

        const bf16* KHs = A_KV(buf, 0);
        const bf16* KLs = A_KV(buf, 1);
        const bf16* VHs = A_KV(buf, 2);
        const bf16* VLs = A_KV(buf, 3);
        const int* np = m_np(buf);
        const int* bt = m_bt(buf);

        unsigned pah[4][4], pal[4][4];    // PV A-frags per 16-key chunk

#pragma unroll
        for (int ntp = 0; ntp < 4; ntp++) {
            float sc[2][4];
#pragma unroll
            for (int q = 0; q < 2; q++)
#pragma unroll
                for (int i = 0; i < 4; i++) sc[q][i] = 0.0f;

#pragma unroll
            for (int kc = 0; kc < 4; kc++) {
                const int nrow = ntp * 16 + (tile >> 1) * 8 + trow;
                const int koff = kc * 16 + (tile & 1) * 8;
                unsigned bh[4], bl[4];
                ldsm4(bh, &KHs[nrow * ASLD + koff]);
                ldsm4(bl, &KLs[nrow * ASLD + koff]);
#pragma unroll
                for (int q = 0; q < 2; q++) {
                    unsigned b0 = bh[q * 2], b1 = bh[q * 2 + 1];
                    unsigned c0 = bl[q * 2], c1 = bl[q * 2 + 1];
                    mma_bf16(sc[q], aqh[kc], b0, b1);
                    mma_bf16(sc[q], aqh[kc], c0, c1);
                    mma_bf16(sc[q], aql[kc], b0, b1);
                }
            }

            // softmax on this 16-key chunk; build PV A-frags in registers
#pragma unroll
            for (int q = 0; q < 2; q++) {
                const int nt = ntp * 2 + q;
                const int col0 = nt * 8 + 2 * t;
                const int cb0 = (np[col0] == 0) | (bt[col0] == 1);
                const int cb1 = (np[col0 + 1] == 0) | (bt[col0 + 1] == 1);
                float x0 = (cb0 | rowbad0) ? -1000.0f : sc[q][0] * scale;
                float x1 = (cb1 | rowbad0) ? -1000.0f : sc[q][1] * scale;
                float x2 = (cb0 | rowbad8) ? -1000.0f : sc[q][2] * scale;
                float x3 = (cb1 | rowbad8) ? -1000.0f : sc[q][3] * scale;
                float p0 = __expf(x0 + shift0);
                float p1 = __expf(x1 + shift0);
                float p2 = __expf(x2 + shift8);
                float p3 = __expf(x3 + shift8);
                lsum0 += p0 + p1;
                lsum8 += p2 + p3;
                bf16 h0, l0, h1, l1, h2, l2, h3, l3;
                split1(p0, h0, l0); split1(p1, h1, l1);
                split1(p2, h2, l2); split1(p3, h3, l3);
                pah[ntp][q * 2 + 0] = pack2(h0, h1);
                pah[ntp][q * 2 + 1] = pack2(h2, h3);
                pal[ntp][q * 2 + 0] = pack2(l0, l1);
                pal[ntp][q * 2 + 1] = pack2(l2, l3);
            }
        }

        // PV: O += P @ V   (V via trans ldmatrix)
#pragma unroll
        for (int kch = 0; kch < 4; kch++) {
            const int keyrow = kch * 16 + (tile & 1) * 8 + trow;
#pragma unroll
            for (int dp = 0; dp < 4; dp++) {
                const int dcol = dp * 16 + (tile >> 1) * 8;
                unsigned bh[4], bl[4];
                ldsm4t(bh, &VHs[keyrow * ASLD + dcol]);
                ldsm4t(bl, &VLs[keyrow * ASLD + dcol]);
#pragma unroll
                for (int q = 0; q < 2; q++) {
                    const int nt = dp * 2 + q;
                    unsigned b0 = bh[q * 2], b1 = bh[q * 2 + 1];
                    unsigned c0 = bl[q * 2], c1 = bl[q * 2 + 1];
                    mma_bf16(O[nt], pah[kch], b0, b1);
                    mma_bf16(O[nt], pah[kch], c0, c1);
                    mma_bf16(O[nt], pal[kch], b0, b1);
                }
            }
        }
        __syncthreads();
        buf ^= 1;
    }

    // epilogue: quad-reduce l, normalize, split-store
    lsum0 += __shfl_xor_sync(0xffffffffu, lsum0, 1);
    lsum0 += __shfl_xor_sync(0xffffffffu, lsum0, 2);
    lsum8 += __shfl_xor_sync(0xffffffffu, lsum8, 1);
    lsum8 += __shfl_xor_sync(0xffffffffu, lsum8, 2);
    const float inv0 = 1.0f / lsum0;
    const float inv8 = 1.0f / lsum8;

    const size_t row0 = (size_t)(b * NN + q0 + rb + g);
    const size_t row8 = row0 + 8;
#pragma unroll
    for (int nt = 0; nt < 8; nt++) {
        const int d = h * 64 + nt * 8 + 2 * t;
        float v0 = O[nt][0] * inv0, v1 = O[nt][1] * inv0;
        float v2 = O[nt][2] * inv8, v3 = O[nt][3] * inv8;
        bf16 h0, l0, h1, l1, h2, l2, h3, l3;
        split1(v0, h0, l0); split1(v1, h1, l1);
        split1(v2, h2, l2); split1(v3, h3, l3);
        *reinterpret_cast<unsigned*>(&outh[row0 * INNER + d]) = pack2(h0, h1);
        *reinterpret_cast<unsigned*>(&outl[row0 * INNER + d]) = pack2(l0, l1);
        *reinterpret_cast<unsigned*>(&outh[row8 * INNER + d]) = pack2(h2, h3);
        *reinterpret_cast<unsigned*>(&outl[row8 * INNER + d]) = pack2(l2, l3);
    }
}

// ---------------------------------------------------------------------------
extern "C" void kernel_launch(void* const* d_in, const int* in_sizes, int n_in,
                              void* d_out, int out_size)
{
    const float* x     = (const float*)d_in[0];
    const int*   mnp   = (const int*)d_in[1];
    const int*   mbert = (const int*)d_in[2];
    const float* Wqkv  = (const float*)d_in[3];
    const float* Wout  = (const float*)d_in[4];
    const float* bout  = (const float*)d_in[5];
    float* out = (float*)d_out;

    bf16 *xh, *xl, *wqh, *wql, *woh, *wol, *qkvh, *qkvl, *ath, *atl;
    cudaGetSymbolAddress((void**)&xh,   g_x_h);
    cudaGetSymbolAddress((void**)&xl,   g_x_l);
    cudaGetSymbolAddress((void**)&wqh,  g_wqkv_h);
    cudaGetSymbolAddress((void**)&wql,  g_wqkv_l);
    cudaGetSymbolAddress((void**)&woh,  g_wout_h);
    cudaGetSymbolAddress((void**)&wol,  g_wout_l);
    cudaGetSymbolAddress((void**)&qkvh, g_qkv_h);
    cudaGetSymbolAddress((void**)&qkvl, g_qkv_l);
    cudaGetSymbolAddress((void**)&ath,  g_att_h);
    cudaGetSymbolAddress((void**)&atl,  g_att_l);

    cudaFuncSetAttribute(gemm_mma, cudaFuncAttributeMaxDynamicSharedMemorySize,
                         GEMM_SMEM_BYTES);
    cudaFuncSetAttribute(attn_mma, cudaFuncAttributeMaxDynamicSharedMemorySize,
                         ATT_SMEM_BYTES);

    // prep: split inputs into bf16 hi/lo
    split_kernel<<<512, 256>>>(x,    xh,  xl,  MROWS * DIM);
    split_kernel<<<512, 256>>>(Wqkv, wqh, wql, DIM * QKV3);
    split_kernel<<<256, 256>>>(Wout, woh, wol, INNER * DIM);

    // 1) qkv = x @ W_qkv  -> bf16 hi/lo
    gemm_mma<<<dim3(QKV3 / 128, MROWS / 128), 256, GEMM_SMEM_BYTES>>>(
        xh, xl, wqh, wql, nullptr, nullptr, qkvh, qkvl, MROWS, QKV3, DIM, 1);

    // 2) masked attention -> bf16 hi/lo
    attn_mma<<<dim3(NN / 128, BB * HH), 256, ATT_SMEM_BYTES>>>(
        qkvh, qkvl, mnp, mbert, ath, atl);

    // 3) out = att @ W_out + b_out  -> fp32
    gemm_mma<<<dim3(DIM / 128, MROWS / 128), 256, GEMM_SMEM_BYTES>>>(
        ath, atl, woh, wol, bout, out, nullptr, nullptr, MROWS, DIM, INNER, 0);
}